// round 14
// baseline (speedup 1.0000x reference)
#include <cuda_runtime.h>
#include <cuda_fp16.h>
#include <cstddef>
#include <cstdint>

// ---------------------------------------------------------------------------
// GCN 3-layer encoder, fp16 pipeline, single-stream schedule.
//   per layer: g = (act(in) @ W) * dinv[row]   (fp16 MMA, fp32 accum)
//              out_i = dinv_i * (sum_{e: dst=i} g[src_e] + g_i) + b  [+ReLU]
// Persistent-block GEMMs. fp32 input path (layer 1) uses register-prefetch
// pipelining: next tile's LDGs issued before MMA, converted+STS next iter.
// fp16 paths use cp.async double-buffering. Aggregation: unroll-8 + HADD2.
// ---------------------------------------------------------------------------

#define N_MAX 100000
#define E_MAX 1600000
#define SCAN_B 1024
#define MAX_SCAN_BLOCKS 128

__device__ __half g_buf[(size_t)N_MAX * 128];
__device__ __half agg_buf[(size_t)N_MAX * 128];
__device__ float dinv_buf[N_MAX];
__device__ int   deg_buf[N_MAX];
__device__ int   rowptr_buf[N_MAX + 1];
__device__ int   cursor_buf[N_MAX];
__device__ int   csrsrc_buf[E_MAX];
__device__ int   blocksum_buf[MAX_SCAN_BLOCKS];
__device__ __half wt1_buf[128 * 128];
__device__ __half wt2_buf[128 * 128];
__device__ __half wt3_buf[64 * 128];

// ---------------- prep: zero deg + W transposes -----------------------------

__global__ void k_prep(const float* __restrict__ W1, const float* __restrict__ W2,
                       const float* __restrict__ W3, int n) {
    int i = blockIdx.x * blockDim.x + threadIdx.x;
    if (i < n) deg_buf[i] = 0;
    if (i < 128 * 128) {
        int k = i >> 7, c = i & 127;
        wt1_buf[c * 128 + k] = __float2half_rn(__ldg(&W1[i]));
        wt2_buf[c * 128 + k] = __float2half_rn(__ldg(&W2[i]));
    }
    if (i < 128 * 64) {
        int k = i >> 6, c = i & 63;
        wt3_buf[c * 128 + k] = __float2half_rn(__ldg(&W3[i]));
    }
}

// -------------------------------- CSR prep --------------------------------

__global__ void k_hist(const int* __restrict__ dst, int e) {
    int i = blockIdx.x * blockDim.x + threadIdx.x;
    if (i < e) atomicAdd(&deg_buf[dst[i]], 1);
}

__global__ __launch_bounds__(SCAN_B) void k_blocksum_dinv(int n) {
    __shared__ int wsum[32];
    int i = blockIdx.x * SCAN_B + threadIdx.x;
    int v = 0;
    if (i < n) {
        v = deg_buf[i];
        dinv_buf[i] = rsqrtf((float)v + 1.0f);
    }
    int s = v;
    #pragma unroll
    for (int off = 16; off > 0; off >>= 1)
        s += __shfl_down_sync(0xffffffffu, s, off);
    int lane = threadIdx.x & 31, w = threadIdx.x >> 5;
    if (lane == 0) wsum[w] = s;
    __syncthreads();
    if (w == 0) {
        int t = wsum[lane];
        #pragma unroll
        for (int off = 16; off > 0; off >>= 1)
            t += __shfl_down_sync(0xffffffffu, t, off);
        if (lane == 0) blocksum_buf[blockIdx.x] = t;
    }
}

__global__ void k_scan_blocksums(int nblocks, int n, int e) {
    __shared__ int wsum[4];
    int t = threadIdx.x;
    int v = (t < nblocks) ? blocksum_buf[t] : 0;
    int lane = t & 31, w = t >> 5;
    int s = v;
    #pragma unroll
    for (int off = 1; off < 32; off <<= 1) {
        int x = __shfl_up_sync(0xffffffffu, s, off);
        if (lane >= off) s += x;
    }
    if (lane == 31) wsum[w] = s;
    __syncthreads();
    int base = 0;
    #pragma unroll
    for (int k = 0; k < 4; k++) base += (k < w) ? wsum[k] : 0;
    if (t < nblocks) blocksum_buf[t] = base + s - v;
    if (t == 0) rowptr_buf[n] = e;
}

__global__ __launch_bounds__(SCAN_B) void k_block_scan(int n) {
    __shared__ int wsum[32];
    int i = blockIdx.x * SCAN_B + threadIdx.x;
    int v = (i < n) ? deg_buf[i] : 0;
    int lane = threadIdx.x & 31, w = threadIdx.x >> 5;
    int s = v;
    #pragma unroll
    for (int off = 1; off < 32; off <<= 1) {
        int x = __shfl_up_sync(0xffffffffu, s, off);
        if (lane >= off) s += x;
    }
    if (lane == 31) wsum[w] = s;
    __syncthreads();
    if (w == 0) {
        int ws = wsum[lane];
        #pragma unroll
        for (int off = 1; off < 32; off <<= 1) {
            int x = __shfl_up_sync(0xffffffffu, ws, off);
            if (lane >= off) ws += x;
        }
        wsum[lane] = ws;
    }
    __syncthreads();
    int warpBase = (w > 0) ? wsum[w - 1] : 0;
    if (i < n) {
        int p = blocksum_buf[blockIdx.x] + warpBase + (s - v);
        rowptr_buf[i] = p;
        cursor_buf[i] = p;
    }
}

__global__ void k_scatter(const int* __restrict__ src, const int* __restrict__ dst, int e) {
    int i = blockIdx.x * blockDim.x + threadIdx.x;
    if (i < e) {
        int d = dst[i];
        int pos = atomicAdd(&cursor_buf[d], 1);
        csrsrc_buf[pos] = src[i];
    }
}

// ----------------------- fp16 tensor-core GEMM -----------------------------

__device__ __forceinline__ void ldsm_x4(uint32_t& r0, uint32_t& r1,
                                        uint32_t& r2, uint32_t& r3, uint32_t addr) {
    asm volatile("ldmatrix.sync.aligned.m8n8.x4.shared.b16 {%0,%1,%2,%3}, [%4];"
                 : "=r"(r0), "=r"(r1), "=r"(r2), "=r"(r3) : "r"(addr));
}

template <int DOUT, typename TIN>
__global__ __launch_bounds__(256) void k_gemm_tc(const TIN* __restrict__ X,
                                                 const __half* __restrict__ Wt,
                                                 __half* __restrict__ G,
                                                 int n, int tiles) {
    constexpr bool HALF_IN = (sizeof(TIN) == 2);
    constexpr int DIN = 128;
    constexpr int WN = DOUT / 32;
    constexpr int WM = 8 / WN;
    constexpr int MB = WM * 32;
    constexpr int XS = 136;
    constexpr int WKS = 136;
    constexpr int XTILE = MB * XS;
    constexpr int NBUF = HALF_IN ? 2 : 1;
    constexpr int PFI = (MB * DIN) / (256 * 8);   // prefetch iters (fp32 path)

    extern __shared__ __half hsm[];
    __half* Ws = hsm;
    __half* Xb[2] = { hsm + DOUT * WKS,
                      hsm + DOUT * WKS + (NBUF == 2 ? XTILE : 0) };

    int t = threadIdx.x;
    int warp = t >> 5, lane = t & 31;
    int wm = warp / WN, wn = warp % WN;
    int g = lane >> 2, tg = lane & 3;

    #pragma unroll
    for (int i = t * 8; i < DOUT * DIN; i += 256 * 8) {
        int c = i >> 7, k = i & 127;
        uint4 v = __ldg((const uint4*)(Wt + i));
        *(uint4*)&Ws[c * WKS + k] = v;
    }

    auto stage_async = [&](int tile, __half* buf) {
        int rowBase = tile * MB;
        #pragma unroll
        for (int i = t * 8; i < MB * DIN; i += 256 * 8) {
            int r = i >> 7, c = i & 127;
            int row = rowBase + r;
            uint32_t saddr = (uint32_t)__cvta_generic_to_shared(&buf[r * XS + c]);
            const __half* gp = (const __half*)X + (size_t)(row < n ? row : 0) * DIN + c;
            int sz = (row < n) ? 16 : 0;
            asm volatile("cp.async.cg.shared.global [%0], [%1], 16, %2;"
                         :: "r"(saddr), "l"(gp), "r"(sz) : "memory");
        }
        asm volatile("cp.async.commit_group;" ::: "memory");
    };

    // fp32 register-prefetch helpers.
    float4 pf[PFI][2];
    auto ldg_tile = [&](int tile) {
        int rowBase = tile * MB;
        #pragma unroll
        for (int it = 0; it < PFI; it++) {
            int i = t * 8 + it * 2048;
            int r = i >> 7, c = i & 127;
            int row = rowBase + r;
            if (row < n) {
                const float* xp = (const float*)X + (size_t)row * DIN + c;
                pf[it][0] = __ldg((const float4*)xp);
                pf[it][1] = __ldg((const float4*)(xp + 4));
            } else {
                pf[it][0] = make_float4(0.f, 0.f, 0.f, 0.f);
                pf[it][1] = make_float4(0.f, 0.f, 0.f, 0.f);
            }
        }
    };
    auto sts_tile = [&](__half* buf) {
        #pragma unroll
        for (int it = 0; it < PFI; it++) {
            int i = t * 8 + it * 2048;
            int r = i >> 7, c = i & 127;
            half2 h0 = __floats2half2_rn(pf[it][0].x, pf[it][0].y);
            half2 h1 = __floats2half2_rn(pf[it][0].z, pf[it][0].w);
            half2 h2 = __floats2half2_rn(pf[it][1].x, pf[it][1].y);
            half2 h3 = __floats2half2_rn(pf[it][1].z, pf[it][1].w);
            uint4 u = make_uint4(*(uint32_t*)&h0, *(uint32_t*)&h1,
                                 *(uint32_t*)&h2, *(uint32_t*)&h3);
            *(uint4*)&buf[r * XS + c] = u;
        }
    };

    uint32_t ws_base = (uint32_t)__cvta_generic_to_shared(Ws);
    uint32_t b_addr = ws_base + (uint32_t)(((wn * 32 + lane) * WKS) * 2);

    int tile = blockIdx.x;
    int cur = 0;
    if (HALF_IN) {
        if (tile < tiles) stage_async(tile, Xb[0]);
    } else {
        if (tile < tiles) ldg_tile(tile);
    }

    for (; tile < tiles; tile += gridDim.x) {
        int nxt = tile + gridDim.x;
        if constexpr (HALF_IN) {
            if (nxt < tiles) stage_async(nxt, Xb[cur ^ 1]);
            if (nxt < tiles)
                asm volatile("cp.async.wait_group 1;" ::: "memory");
            else
                asm volatile("cp.async.wait_group 0;" ::: "memory");
            __syncthreads();
        } else {
            __syncthreads();              // prior tile's MMA reads done
            sts_tile(Xb[0]);              // consume prefetched regs
            __syncthreads();              // tile visible
            if (nxt < tiles) ldg_tile(nxt);  // overlap with MMA below
        }

        __half* Xs = Xb[cur];
        uint32_t xs_base = (uint32_t)__cvta_generic_to_shared(Xs);
        uint32_t a_addr0 = xs_base + (uint32_t)(((wm * 32 + (lane & 15)) * XS + ((lane >> 4) << 3)) * 2);
        uint32_t a_addr1 = a_addr0 + (uint32_t)(16 * XS * 2);

        float acc[2][4][4];
        #pragma unroll
        for (int a = 0; a < 2; a++)
            #pragma unroll
            for (int u = 0; u < 4; u++)
                #pragma unroll
                for (int k = 0; k < 4; k++) acc[a][u][k] = 0.f;

        #pragma unroll
        for (int ks = 0; ks < DIN / 16; ks++) {
            uint32_t koff = (uint32_t)(ks * 32);
            uint32_t a[2][4], b0[4], b1[4];
            ldsm_x4(a[0][0], a[0][1], a[0][2], a[0][3], a_addr0 + koff);
            ldsm_x4(a[1][0], a[1][1], a[1][2], a[1][3], a_addr1 + koff);
            ldsm_x4(b0[0], b0[1], b0[2], b0[3], b_addr + koff);
            ldsm_x4(b1[0], b1[1], b1[2], b1[3], b_addr + koff + 16);
            #pragma unroll
            for (int tt = 0; tt < 2; tt++)
                #pragma unroll
                for (int u = 0; u < 4; u++) {
                    asm volatile(
                        "mma.sync.aligned.m16n8k16.row.col.f32.f16.f16.f32 "
                        "{%0,%1,%2,%3}, {%4,%5,%6,%7}, {%8,%9}, {%0,%1,%2,%3};"
                        : "+f"(acc[tt][u][0]), "+f"(acc[tt][u][1]),
                          "+f"(acc[tt][u][2]), "+f"(acc[tt][u][3])
                        : "r"(a[tt][0]), "r"(a[tt][1]), "r"(a[tt][2]), "r"(a[tt][3]),
                          "r"(b0[u]), "r"(b1[u]));
                }
        }

        int rowBase = tile * MB;
        #pragma unroll
        for (int tt = 0; tt < 2; tt++) {
            int r0 = rowBase + wm * 32 + tt * 16 + g;
            int r1 = r0 + 8;
            int cbase = wn * 32 + 2 * tg;
            if (r0 < n) {
                float di = dinv_buf[r0];
                #pragma unroll
                for (int u = 0; u < 4; u++) {
                    half2 h = __floats2half2_rn(acc[tt][u][0] * di, acc[tt][u][1] * di);
                    *(half2*)(G + (size_t)r0 * DOUT + cbase + u * 8) = h;
                }
            }
            if (r1 < n) {
                float di = dinv_buf[r1];
                #pragma unroll
                for (int u = 0; u < 4; u++) {
                    half2 h = __floats2half2_rn(acc[tt][u][2] * di, acc[tt][u][3] * di);
                    *(half2*)(G + (size_t)r1 * DOUT + cbase + u * 8) = h;
                }
            }
        }
        if constexpr (HALF_IN) {
            __syncthreads();
            cur ^= 1;
        }
    }
}

// ------------------------------ Aggregation --------------------------------

template <int D, bool RELU, typename TOUT>
__global__ __launch_bounds__(256) void k_aggregate(const __half* __restrict__ G,
                                                   const float* __restrict__ bias,
                                                   TOUT* __restrict__ OUT, int n) {
    int wid = (blockIdx.x * blockDim.x + threadIdx.x) >> 5;
    int lane = threadIdx.x & 31;
    if (wid >= n) return;
    constexpr int V = D / 32;

    float acc[V];
    if constexpr (V == 4) {
        uint2 a = *(const uint2*)(G + (size_t)wid * D + lane * 4);
        float2 f0 = __half22float2(*(half2*)&a.x);
        float2 f1 = __half22float2(*(half2*)&a.y);
        acc[0] = f0.x; acc[1] = f0.y; acc[2] = f1.x; acc[3] = f1.y;
    } else {
        uint32_t a = *(const uint32_t*)(G + (size_t)wid * D + lane * 2);
        float2 f = __half22float2(*(half2*)&a);
        acc[0] = f.x; acc[1] = f.y;
    }

    int s0 = rowptr_buf[wid];
    int s1 = rowptr_buf[wid + 1];

    int j = s0;
    for (; j + 7 < s1; j += 8) {
        int si[8];
        #pragma unroll
        for (int q = 0; q < 8; q++) si[q] = __ldg(&csrsrc_buf[j + q]);
        if constexpr (V == 4) {
            uint2 r[8];
            #pragma unroll
            for (int q = 0; q < 8; q++)
                r[q] = __ldg((const uint2*)(G + (size_t)si[q] * D) + lane);
            half2 sx0 = __hadd2(__hadd2(*(half2*)&r[0].x, *(half2*)&r[1].x),
                                __hadd2(*(half2*)&r[2].x, *(half2*)&r[3].x));
            half2 sy0 = __hadd2(__hadd2(*(half2*)&r[0].y, *(half2*)&r[1].y),
                                __hadd2(*(half2*)&r[2].y, *(half2*)&r[3].y));
            half2 sx1 = __hadd2(__hadd2(*(half2*)&r[4].x, *(half2*)&r[5].x),
                                __hadd2(*(half2*)&r[6].x, *(half2*)&r[7].x));
            half2 sy1 = __hadd2(__hadd2(*(half2*)&r[4].y, *(half2*)&r[5].y),
                                __hadd2(*(half2*)&r[6].y, *(half2*)&r[7].y));
            float2 fx0 = __half22float2(sx0), fy0 = __half22float2(sy0);
            float2 fx1 = __half22float2(sx1), fy1 = __half22float2(sy1);
            acc[0] += fx0.x + fx1.x; acc[1] += fx0.y + fx1.y;
            acc[2] += fy0.x + fy1.x; acc[3] += fy0.y + fy1.y;
        } else {
            uint32_t r[8];
            #pragma unroll
            for (int q = 0; q < 8; q++)
                r[q] = __ldg((const uint32_t*)(G + (size_t)si[q] * D) + lane);
            half2 s0h = __hadd2(__hadd2(*(half2*)&r[0], *(half2*)&r[1]),
                                __hadd2(*(half2*)&r[2], *(half2*)&r[3]));
            half2 s1h = __hadd2(__hadd2(*(half2*)&r[4], *(half2*)&r[5]),
                                __hadd2(*(half2*)&r[6], *(half2*)&r[7]));
            float2 f0 = __half22float2(s0h), f1 = __half22float2(s1h);
            acc[0] += f0.x + f1.x; acc[1] += f0.y + f1.y;
        }
    }
    for (; j + 3 < s1; j += 4) {
        int sa = __ldg(&csrsrc_buf[j]);
        int sb = __ldg(&csrsrc_buf[j + 1]);
        int sc = __ldg(&csrsrc_buf[j + 2]);
        int sd = __ldg(&csrsrc_buf[j + 3]);
        if constexpr (V == 4) {
            uint2 a = __ldg((const uint2*)(G + (size_t)sa * D) + lane);
            uint2 b = __ldg((const uint2*)(G + (size_t)sb * D) + lane);
            uint2 c = __ldg((const uint2*)(G + (size_t)sc * D) + lane);
            uint2 d = __ldg((const uint2*)(G + (size_t)sd * D) + lane);
            half2 sx = __hadd2(__hadd2(*(half2*)&a.x, *(half2*)&b.x),
                               __hadd2(*(half2*)&c.x, *(half2*)&d.x));
            half2 sy = __hadd2(__hadd2(*(half2*)&a.y, *(half2*)&b.y),
                               __hadd2(*(half2*)&c.y, *(half2*)&d.y));
            float2 fx = __half22float2(sx);
            float2 fy = __half22float2(sy);
            acc[0] += fx.x; acc[1] += fx.y; acc[2] += fy.x; acc[3] += fy.y;
        } else {
            uint32_t a = __ldg((const uint32_t*)(G + (size_t)sa * D) + lane);
            uint32_t b = __ldg((const uint32_t*)(G + (size_t)sb * D) + lane);
            uint32_t c = __ldg((const uint32_t*)(G + (size_t)sc * D) + lane);
            uint32_t d = __ldg((const uint32_t*)(G + (size_t)sd * D) + lane);
            half2 sx = __hadd2(__hadd2(*(half2*)&a, *(half2*)&b),
                               __hadd2(*(half2*)&c, *(half2*)&d));
            float2 fx = __half22float2(sx);
            acc[0] += fx.x; acc[1] += fx.y;
        }
    }
    for (; j < s1; j++) {
        int s = __ldg(&csrsrc_buf[j]);
        if constexpr (V == 4) {
            uint2 a = __ldg((const uint2*)(G + (size_t)s * D) + lane);
            float2 f0 = __half22float2(*(half2*)&a.x), f1 = __half22float2(*(half2*)&a.y);
            acc[0] += f0.x; acc[1] += f0.y; acc[2] += f1.x; acc[3] += f1.y;
        } else {
            uint32_t a = __ldg((const uint32_t*)(G + (size_t)s * D) + lane);
            float2 f = __half22float2(*(half2*)&a);
            acc[0] += f.x; acc[1] += f.y;
        }
    }

    float di = dinv_buf[wid];
    if constexpr (V == 4) {
        float4 b = __ldg((const float4*)bias + lane);
        float o0 = acc[0] * di + b.x, o1 = acc[1] * di + b.y;
        float o2 = acc[2] * di + b.z, o3 = acc[3] * di + b.w;
        if (RELU) {
            o0 = fmaxf(o0, 0.f); o1 = fmaxf(o1, 0.f);
            o2 = fmaxf(o2, 0.f); o3 = fmaxf(o3, 0.f);
        }
        if constexpr (sizeof(TOUT) == 2) {
            __half* op = (__half*)OUT + (size_t)wid * D + lane * 4;
            *(half2*)op = __floats2half2_rn(o0, o1);
            *(half2*)(op + 2) = __floats2half2_rn(o2, o3);
        } else {
            float* op = (float*)OUT + (size_t)wid * D + lane * 4;
            *(float4*)op = make_float4(o0, o1, o2, o3);
        }
    } else {
        float2 b = __ldg((const float2*)bias + lane);
        float o0 = acc[0] * di + b.x, o1 = acc[1] * di + b.y;
        if (RELU) { o0 = fmaxf(o0, 0.f); o1 = fmaxf(o1, 0.f); }
        if constexpr (sizeof(TOUT) == 2) {
            __half* op = (__half*)OUT + (size_t)wid * D + lane * 2;
            *(half2*)op = __floats2half2_rn(o0, o1);
        } else {
            float* op = (float*)OUT + (size_t)wid * D + lane * 2;
            *(float2*)op = make_float2(o0, o1);
        }
    }
}

// ------------------------------- launch ------------------------------------

extern "C" void kernel_launch(void* const* d_in, const int* in_sizes, int n_in,
                              void* d_out, int out_size) {
    const float* x  = (const float*)d_in[0];
    const int*   ei = (const int*)d_in[1];
    const float* W1 = (const float*)d_in[2];
    const float* b1 = (const float*)d_in[3];
    const float* W2 = (const float*)d_in[4];
    const float* b2 = (const float*)d_in[5];
    const float* W3 = (const float*)d_in[6];
    const float* b3 = (const float*)d_in[7];

    int n = in_sizes[0] / 128;
    int e = in_sizes[1] / 2;
    const int* src = ei;
    const int* dst = ei + e;

    __half *g, *agg, *wt1, *wt2, *wt3;
    cudaGetSymbolAddress((void**)&g, g_buf);
    cudaGetSymbolAddress((void**)&agg, agg_buf);
    cudaGetSymbolAddress((void**)&wt1, wt1_buf);
    cudaGetSymbolAddress((void**)&wt2, wt2_buf);
    cudaGetSymbolAddress((void**)&wt3, wt3_buf);
    float* out = (float*)d_out;

    int nb = (n + 255) / 256;
    int eb = (e + 255) / 256;
    int scan_blocks = (n + SCAN_B - 1) / SCAN_B;

    constexpr int SMEM1 = (128 * 136 + 1 * 64 * 136) * 2;
    constexpr int SMEM2 = (128 * 136 + 2 * 64 * 136) * 2;
    constexpr int SMEM3 = (64 * 136 + 2 * 128 * 136) * 2;
    cudaFuncSetAttribute(k_gemm_tc<128, float>,  cudaFuncAttributeMaxDynamicSharedMemorySize, SMEM1);
    cudaFuncSetAttribute(k_gemm_tc<128, __half>, cudaFuncAttributeMaxDynamicSharedMemorySize, SMEM2);
    cudaFuncSetAttribute(k_gemm_tc<64,  __half>, cudaFuncAttributeMaxDynamicSharedMemorySize, SMEM3);

    int tiles128 = (n + 63) / 64;
    int tiles64  = (n + 127) / 128;
    int grid1   = tiles128 < 296 ? tiles128 : 296;   // fp32 path: ~106 regs, 2/SM
    int grid128 = tiles128 < 444 ? tiles128 : 444;   // fp16 paths: 3/SM
    int grid64  = tiles64  < 296 ? tiles64  : 296;

    // Single stream; GEMM1 is launch #4 (ncu captures launch 4).
    k_prep<<<nb, 256>>>(W1, W2, W3, n);                                   // 1
    k_hist<<<eb, 256>>>(dst, e);                                          // 2
    k_blocksum_dinv<<<scan_blocks, SCAN_B>>>(n);                          // 3
    k_gemm_tc<128, float><<<grid1, 256, SMEM1>>>(x, wt1, g, n, tiles128); // 4
    k_scan_blocksums<<<1, MAX_SCAN_BLOCKS>>>(scan_blocks, n, e);
    k_block_scan<<<scan_blocks, SCAN_B>>>(n);
    k_scatter<<<eb, 256>>>(src, dst, e);

    int agg_blocks = (n * 32 + 255) / 256;

    k_aggregate<128, true, __half><<<agg_blocks, 256>>>(g, b1, agg, n);

    k_gemm_tc<128, __half><<<grid128, 256, SMEM2>>>(agg, wt2, g, n, tiles128);
    k_aggregate<128, true, __half><<<agg_blocks, 256>>>(g, b2, agg, n);

    k_gemm_tc<64, __half><<<grid64, 256, SMEM3>>>(agg, wt3, g, n, tiles64);
    k_aggregate<64, false, float><<<agg_blocks, 256>>>(g, b3, out, n);
}

// round 16
// speedup vs baseline: 1.0219x; 1.0219x over previous
#include <cuda_runtime.h>
#include <cuda_fp16.h>
#include <cstddef>
#include <cstdint>

// ---------------------------------------------------------------------------
// GCN 3-layer encoder, fp16 pipeline.
//   per layer: g = (act(in) @ W) * dinv[row]   (fp16 MMA, fp32 accum)
//              out_i = dinv_i * (sum_{e: dst=i} g[src_e] + g_i) + b  [+ReLU]
// Persistent-block GEMMs. Aggregation: unroll-8 + fp16 HADD2 trees.
// Schedule: CSR tail (scan/scatter) forked onto a side stream, hidden under
// GEMM1 (which only needs dinv, ready before the fork).
// ---------------------------------------------------------------------------

#define N_MAX 100000
#define E_MAX 1600000
#define SCAN_B 1024
#define MAX_SCAN_BLOCKS 128

__device__ __half g_buf[(size_t)N_MAX * 128];
__device__ __half agg_buf[(size_t)N_MAX * 128];
__device__ float dinv_buf[N_MAX];
__device__ int   deg_buf[N_MAX];
__device__ int   rowptr_buf[N_MAX + 1];
__device__ int   cursor_buf[N_MAX];
__device__ int   csrsrc_buf[E_MAX];
__device__ int   blocksum_buf[MAX_SCAN_BLOCKS];
__device__ __half wt1_buf[128 * 128];
__device__ __half wt2_buf[128 * 128];
__device__ __half wt3_buf[64 * 128];

// ---------------- prep: zero deg + W transposes -----------------------------

__global__ void k_prep(const float* __restrict__ W1, const float* __restrict__ W2,
                       const float* __restrict__ W3, int n) {
    int i = blockIdx.x * blockDim.x + threadIdx.x;
    if (i < n) deg_buf[i] = 0;
    if (i < 128 * 128) {
        int k = i >> 7, c = i & 127;
        wt1_buf[c * 128 + k] = __float2half_rn(__ldg(&W1[i]));
        wt2_buf[c * 128 + k] = __float2half_rn(__ldg(&W2[i]));
    }
    if (i < 128 * 64) {
        int k = i >> 6, c = i & 63;
        wt3_buf[c * 128 + k] = __float2half_rn(__ldg(&W3[i]));
    }
}

// -------------------------------- CSR prep --------------------------------

__global__ void k_hist(const int* __restrict__ dst, int e) {
    int i = blockIdx.x * blockDim.x + threadIdx.x;
    if (i < e) atomicAdd(&deg_buf[dst[i]], 1);
}

__global__ __launch_bounds__(SCAN_B) void k_blocksum_dinv(int n) {
    __shared__ int wsum[32];
    int i = blockIdx.x * SCAN_B + threadIdx.x;
    int v = 0;
    if (i < n) {
        v = deg_buf[i];
        dinv_buf[i] = rsqrtf((float)v + 1.0f);
    }
    int s = v;
    #pragma unroll
    for (int off = 16; off > 0; off >>= 1)
        s += __shfl_down_sync(0xffffffffu, s, off);
    int lane = threadIdx.x & 31, w = threadIdx.x >> 5;
    if (lane == 0) wsum[w] = s;
    __syncthreads();
    if (w == 0) {
        int t = wsum[lane];
        #pragma unroll
        for (int off = 16; off > 0; off >>= 1)
            t += __shfl_down_sync(0xffffffffu, t, off);
        if (lane == 0) blocksum_buf[blockIdx.x] = t;
    }
}

__global__ void k_scan_blocksums(int nblocks, int n, int e) {
    __shared__ int wsum[4];
    int t = threadIdx.x;
    int v = (t < nblocks) ? blocksum_buf[t] : 0;
    int lane = t & 31, w = t >> 5;
    int s = v;
    #pragma unroll
    for (int off = 1; off < 32; off <<= 1) {
        int x = __shfl_up_sync(0xffffffffu, s, off);
        if (lane >= off) s += x;
    }
    if (lane == 31) wsum[w] = s;
    __syncthreads();
    int base = 0;
    #pragma unroll
    for (int k = 0; k < 4; k++) base += (k < w) ? wsum[k] : 0;
    if (t < nblocks) blocksum_buf[t] = base + s - v;
    if (t == 0) rowptr_buf[n] = e;
}

__global__ __launch_bounds__(SCAN_B) void k_block_scan(int n) {
    __shared__ int wsum[32];
    int i = blockIdx.x * SCAN_B + threadIdx.x;
    int v = (i < n) ? deg_buf[i] : 0;
    int lane = threadIdx.x & 31, w = threadIdx.x >> 5;
    int s = v;
    #pragma unroll
    for (int off = 1; off < 32; off <<= 1) {
        int x = __shfl_up_sync(0xffffffffu, s, off);
        if (lane >= off) s += x;
    }
    if (lane == 31) wsum[w] = s;
    __syncthreads();
    if (w == 0) {
        int ws = wsum[lane];
        #pragma unroll
        for (int off = 1; off < 32; off <<= 1) {
            int x = __shfl_up_sync(0xffffffffu, ws, off);
            if (lane >= off) ws += x;
        }
        wsum[lane] = ws;
    }
    __syncthreads();
    int warpBase = (w > 0) ? wsum[w - 1] : 0;
    if (i < n) {
        int p = blocksum_buf[blockIdx.x] + warpBase + (s - v);
        rowptr_buf[i] = p;
        cursor_buf[i] = p;
    }
}

__global__ void k_scatter(const int* __restrict__ src, const int* __restrict__ dst, int e) {
    int i = blockIdx.x * blockDim.x + threadIdx.x;
    if (i < e) {
        int d = dst[i];
        int pos = atomicAdd(&cursor_buf[d], 1);
        csrsrc_buf[pos] = src[i];
    }
}

// ----------------------- fp16 tensor-core GEMM -----------------------------

__device__ __forceinline__ void ldsm_x4(uint32_t& r0, uint32_t& r1,
                                        uint32_t& r2, uint32_t& r3, uint32_t addr) {
    asm volatile("ldmatrix.sync.aligned.m8n8.x4.shared.b16 {%0,%1,%2,%3}, [%4];"
                 : "=r"(r0), "=r"(r1), "=r"(r2), "=r"(r3) : "r"(addr));
}

template <int DOUT, typename TIN>
__global__ __launch_bounds__(256) void k_gemm_tc(const TIN* __restrict__ X,
                                                 const __half* __restrict__ Wt,
                                                 __half* __restrict__ G,
                                                 int n, int tiles) {
    constexpr bool HALF_IN = (sizeof(TIN) == 2);
    constexpr int DIN = 128;
    constexpr int WN = DOUT / 32;
    constexpr int WM = 8 / WN;
    constexpr int MB = WM * 32;
    constexpr int XS = 136;
    constexpr int WKS = 136;
    constexpr int XTILE = MB * XS;
    constexpr int NBUF = HALF_IN ? 2 : 1;

    extern __shared__ __half hsm[];
    __half* Ws = hsm;
    __half* Xb[2] = { hsm + DOUT * WKS,
                      hsm + DOUT * WKS + (NBUF == 2 ? XTILE : 0) };

    int t = threadIdx.x;
    int warp = t >> 5, lane = t & 31;
    int wm = warp / WN, wn = warp % WN;
    int g = lane >> 2, tg = lane & 3;

    #pragma unroll
    for (int i = t * 8; i < DOUT * DIN; i += 256 * 8) {
        int c = i >> 7, k = i & 127;
        uint4 v = __ldg((const uint4*)(Wt + i));
        *(uint4*)&Ws[c * WKS + k] = v;
    }

    auto stage_async = [&](int tile, __half* buf) {
        int rowBase = tile * MB;
        #pragma unroll
        for (int i = t * 8; i < MB * DIN; i += 256 * 8) {
            int r = i >> 7, c = i & 127;
            int row = rowBase + r;
            uint32_t saddr = (uint32_t)__cvta_generic_to_shared(&buf[r * XS + c]);
            const __half* gp = (const __half*)X + (size_t)(row < n ? row : 0) * DIN + c;
            int sz = (row < n) ? 16 : 0;
            asm volatile("cp.async.cg.shared.global [%0], [%1], 16, %2;"
                         :: "r"(saddr), "l"(gp), "r"(sz) : "memory");
        }
        asm volatile("cp.async.commit_group;" ::: "memory");
    };
    auto stage_f32 = [&](int tile, __half* buf) {
        int rowBase = tile * MB;
        #pragma unroll
        for (int i = t * 8; i < MB * DIN; i += 256 * 8) {
            int r = i >> 7, c = i & 127;
            int row = rowBase + r;
            uint4 u;
            if (row < n) {
                const float* xp = (const float*)X + (size_t)row * DIN + c;
                float4 v0 = __ldg((const float4*)xp);
                float4 v1 = __ldg((const float4*)(xp + 4));
                half2 h0 = __floats2half2_rn(v0.x, v0.y);
                half2 h1 = __floats2half2_rn(v0.z, v0.w);
                half2 h2 = __floats2half2_rn(v1.x, v1.y);
                half2 h3 = __floats2half2_rn(v1.z, v1.w);
                u = make_uint4(*(uint32_t*)&h0, *(uint32_t*)&h1,
                               *(uint32_t*)&h2, *(uint32_t*)&h3);
            } else u = make_uint4(0u, 0u, 0u, 0u);
            *(uint4*)&buf[r * XS + c] = u;
        }
    };

    uint32_t ws_base = (uint32_t)__cvta_generic_to_shared(Ws);
    uint32_t b_addr = ws_base + (uint32_t)(((wn * 32 + lane) * WKS) * 2);

    int tile = blockIdx.x;
    int cur = 0;
    if (HALF_IN && tile < tiles) stage_async(tile, Xb[0]);

    for (; tile < tiles; tile += gridDim.x) {
        if constexpr (HALF_IN) {
            int nxt = tile + gridDim.x;
            if (nxt < tiles) stage_async(nxt, Xb[cur ^ 1]);
            if (nxt < tiles)
                asm volatile("cp.async.wait_group 1;" ::: "memory");
            else
                asm volatile("cp.async.wait_group 0;" ::: "memory");
            __syncthreads();
        } else {
            __syncthreads();
            stage_f32(tile, Xb[0]);
            __syncthreads();
        }

        __half* Xs = Xb[cur];
        uint32_t xs_base = (uint32_t)__cvta_generic_to_shared(Xs);
        uint32_t a_addr0 = xs_base + (uint32_t)(((wm * 32 + (lane & 15)) * XS + ((lane >> 4) << 3)) * 2);
        uint32_t a_addr1 = a_addr0 + (uint32_t)(16 * XS * 2);

        float acc[2][4][4];
        #pragma unroll
        for (int a = 0; a < 2; a++)
            #pragma unroll
            for (int u = 0; u < 4; u++)
                #pragma unroll
                for (int k = 0; k < 4; k++) acc[a][u][k] = 0.f;

        #pragma unroll
        for (int ks = 0; ks < DIN / 16; ks++) {
            uint32_t koff = (uint32_t)(ks * 32);
            uint32_t a[2][4], b0[4], b1[4];
            ldsm_x4(a[0][0], a[0][1], a[0][2], a[0][3], a_addr0 + koff);
            ldsm_x4(a[1][0], a[1][1], a[1][2], a[1][3], a_addr1 + koff);
            ldsm_x4(b0[0], b0[1], b0[2], b0[3], b_addr + koff);
            ldsm_x4(b1[0], b1[1], b1[2], b1[3], b_addr + koff + 16);
            #pragma unroll
            for (int tt = 0; tt < 2; tt++)
                #pragma unroll
                for (int u = 0; u < 4; u++) {
                    asm volatile(
                        "mma.sync.aligned.m16n8k16.row.col.f32.f16.f16.f32 "
                        "{%0,%1,%2,%3}, {%4,%5,%6,%7}, {%8,%9}, {%0,%1,%2,%3};"
                        : "+f"(acc[tt][u][0]), "+f"(acc[tt][u][1]),
                          "+f"(acc[tt][u][2]), "+f"(acc[tt][u][3])
                        : "r"(a[tt][0]), "r"(a[tt][1]), "r"(a[tt][2]), "r"(a[tt][3]),
                          "r"(b0[u]), "r"(b1[u]));
                }
        }

        int rowBase = tile * MB;
        #pragma unroll
        for (int tt = 0; tt < 2; tt++) {
            int r0 = rowBase + wm * 32 + tt * 16 + g;
            int r1 = r0 + 8;
            int cbase = wn * 32 + 2 * tg;
            if (r0 < n) {
                float di = dinv_buf[r0];
                #pragma unroll
                for (int u = 0; u < 4; u++) {
                    half2 h = __floats2half2_rn(acc[tt][u][0] * di, acc[tt][u][1] * di);
                    *(half2*)(G + (size_t)r0 * DOUT + cbase + u * 8) = h;
                }
            }
            if (r1 < n) {
                float di = dinv_buf[r1];
                #pragma unroll
                for (int u = 0; u < 4; u++) {
                    half2 h = __floats2half2_rn(acc[tt][u][2] * di, acc[tt][u][3] * di);
                    *(half2*)(G + (size_t)r1 * DOUT + cbase + u * 8) = h;
                }
            }
        }
        if constexpr (HALF_IN) {
            __syncthreads();
            cur ^= 1;
        }
    }
}

// ------------------------------ Aggregation --------------------------------

template <int D, bool RELU, typename TOUT>
__global__ __launch_bounds__(256) void k_aggregate(const __half* __restrict__ G,
                                                   const float* __restrict__ bias,
                                                   TOUT* __restrict__ OUT, int n) {
    int wid = (blockIdx.x * blockDim.x + threadIdx.x) >> 5;
    int lane = threadIdx.x & 31;
    if (wid >= n) return;
    constexpr int V = D / 32;

    float acc[V];
    if constexpr (V == 4) {
        uint2 a = *(const uint2*)(G + (size_t)wid * D + lane * 4);
        float2 f0 = __half22float2(*(half2*)&a.x);
        float2 f1 = __half22float2(*(half2*)&a.y);
        acc[0] = f0.x; acc[1] = f0.y; acc[2] = f1.x; acc[3] = f1.y;
    } else {
        uint32_t a = *(const uint32_t*)(G + (size_t)wid * D + lane * 2);
        float2 f = __half22float2(*(half2*)&a);
        acc[0] = f.x; acc[1] = f.y;
    }

    int s0 = rowptr_buf[wid];
    int s1 = rowptr_buf[wid + 1];

    int j = s0;
    for (; j + 7 < s1; j += 8) {
        int si[8];
        #pragma unroll
        for (int q = 0; q < 8; q++) si[q] = __ldg(&csrsrc_buf[j + q]);
        if constexpr (V == 4) {
            uint2 r[8];
            #pragma unroll
            for (int q = 0; q < 8; q++)
                r[q] = __ldg((const uint2*)(G + (size_t)si[q] * D) + lane);
            half2 sx0 = __hadd2(__hadd2(*(half2*)&r[0].x, *(half2*)&r[1].x),
                                __hadd2(*(half2*)&r[2].x, *(half2*)&r[3].x));
            half2 sy0 = __hadd2(__hadd2(*(half2*)&r[0].y, *(half2*)&r[1].y),
                                __hadd2(*(half2*)&r[2].y, *(half2*)&r[3].y));
            half2 sx1 = __hadd2(__hadd2(*(half2*)&r[4].x, *(half2*)&r[5].x),
                                __hadd2(*(half2*)&r[6].x, *(half2*)&r[7].x));
            half2 sy1 = __hadd2(__hadd2(*(half2*)&r[4].y, *(half2*)&r[5].y),
                                __hadd2(*(half2*)&r[6].y, *(half2*)&r[7].y));
            float2 fx0 = __half22float2(sx0), fy0 = __half22float2(sy0);
            float2 fx1 = __half22float2(sx1), fy1 = __half22float2(sy1);
            acc[0] += fx0.x + fx1.x; acc[1] += fx0.y + fx1.y;
            acc[2] += fy0.x + fy1.x; acc[3] += fy0.y + fy1.y;
        } else {
            uint32_t r[8];
            #pragma unroll
            for (int q = 0; q < 8; q++)
                r[q] = __ldg((const uint32_t*)(G + (size_t)si[q] * D) + lane);
            half2 s0h = __hadd2(__hadd2(*(half2*)&r[0], *(half2*)&r[1]),
                                __hadd2(*(half2*)&r[2], *(half2*)&r[3]));
            half2 s1h = __hadd2(__hadd2(*(half2*)&r[4], *(half2*)&r[5]),
                                __hadd2(*(half2*)&r[6], *(half2*)&r[7]));
            float2 f0 = __half22float2(s0h), f1 = __half22float2(s1h);
            acc[0] += f0.x + f1.x; acc[1] += f0.y + f1.y;
        }
    }
    for (; j + 3 < s1; j += 4) {
        int sa = __ldg(&csrsrc_buf[j]);
        int sb = __ldg(&csrsrc_buf[j + 1]);
        int sc = __ldg(&csrsrc_buf[j + 2]);
        int sd = __ldg(&csrsrc_buf[j + 3]);
        if constexpr (V == 4) {
            uint2 a = __ldg((const uint2*)(G + (size_t)sa * D) + lane);
            uint2 b = __ldg((const uint2*)(G + (size_t)sb * D) + lane);
            uint2 c = __ldg((const uint2*)(G + (size_t)sc * D) + lane);
            uint2 d = __ldg((const uint2*)(G + (size_t)sd * D) + lane);
            half2 sx = __hadd2(__hadd2(*(half2*)&a.x, *(half2*)&b.x),
                               __hadd2(*(half2*)&c.x, *(half2*)&d.x));
            half2 sy = __hadd2(__hadd2(*(half2*)&a.y, *(half2*)&b.y),
                               __hadd2(*(half2*)&c.y, *(half2*)&d.y));
            float2 fx = __half22float2(sx);
            float2 fy = __half22float2(sy);
            acc[0] += fx.x; acc[1] += fx.y; acc[2] += fy.x; acc[3] += fy.y;
        } else {
            uint32_t a = __ldg((const uint32_t*)(G + (size_t)sa * D) + lane);
            uint32_t b = __ldg((const uint32_t*)(G + (size_t)sb * D) + lane);
            uint32_t c = __ldg((const uint32_t*)(G + (size_t)sc * D) + lane);
            uint32_t d = __ldg((const uint32_t*)(G + (size_t)sd * D) + lane);
            half2 sx = __hadd2(__hadd2(*(half2*)&a, *(half2*)&b),
                               __hadd2(*(half2*)&c, *(half2*)&d));
            float2 fx = __half22float2(sx);
            acc[0] += fx.x; acc[1] += fx.y;
        }
    }
    for (; j < s1; j++) {
        int s = __ldg(&csrsrc_buf[j]);
        if constexpr (V == 4) {
            uint2 a = __ldg((const uint2*)(G + (size_t)s * D) + lane);
            float2 f0 = __half22float2(*(half2*)&a.x), f1 = __half22float2(*(half2*)&a.y);
            acc[0] += f0.x; acc[1] += f0.y; acc[2] += f1.x; acc[3] += f1.y;
        } else {
            uint32_t a = __ldg((const uint32_t*)(G + (size_t)s * D) + lane);
            float2 f = __half22float2(*(half2*)&a);
            acc[0] += f.x; acc[1] += f.y;
        }
    }

    float di = dinv_buf[wid];
    if constexpr (V == 4) {
        float4 b = __ldg((const float4*)bias + lane);
        float o0 = acc[0] * di + b.x, o1 = acc[1] * di + b.y;
        float o2 = acc[2] * di + b.z, o3 = acc[3] * di + b.w;
        if (RELU) {
            o0 = fmaxf(o0, 0.f); o1 = fmaxf(o1, 0.f);
            o2 = fmaxf(o2, 0.f); o3 = fmaxf(o3, 0.f);
        }
        if constexpr (sizeof(TOUT) == 2) {
            __half* op = (__half*)OUT + (size_t)wid * D + lane * 4;
            *(half2*)op = __floats2half2_rn(o0, o1);
            *(half2*)(op + 2) = __floats2half2_rn(o2, o3);
        } else {
            float* op = (float*)OUT + (size_t)wid * D + lane * 4;
            *(float4*)op = make_float4(o0, o1, o2, o3);
        }
    } else {
        float2 b = __ldg((const float2*)bias + lane);
        float o0 = acc[0] * di + b.x, o1 = acc[1] * di + b.y;
        if (RELU) { o0 = fmaxf(o0, 0.f); o1 = fmaxf(o1, 0.f); }
        if constexpr (sizeof(TOUT) == 2) {
            __half* op = (__half*)OUT + (size_t)wid * D + lane * 2;
            *(half2*)op = __floats2half2_rn(o0, o1);
        } else {
            float* op = (float*)OUT + (size_t)wid * D + lane * 2;
            *(float2*)op = make_float2(o0, o1);
        }
    }
}

// ------------------------------- launch ------------------------------------

extern "C" void kernel_launch(void* const* d_in, const int* in_sizes, int n_in,
                              void* d_out, int out_size) {
    const float* x  = (const float*)d_in[0];
    const int*   ei = (const int*)d_in[1];
    const float* W1 = (const float*)d_in[2];
    const float* b1 = (const float*)d_in[3];
    const float* W2 = (const float*)d_in[4];
    const float* b2 = (const float*)d_in[5];
    const float* W3 = (const float*)d_in[6];
    const float* b3 = (const float*)d_in[7];

    int n = in_sizes[0] / 128;
    int e = in_sizes[1] / 2;
    const int* src = ei;
    const int* dst = ei + e;

    __half *g, *agg, *wt1, *wt2, *wt3;
    cudaGetSymbolAddress((void**)&g, g_buf);
    cudaGetSymbolAddress((void**)&agg, agg_buf);
    cudaGetSymbolAddress((void**)&wt1, wt1_buf);
    cudaGetSymbolAddress((void**)&wt2, wt2_buf);
    cudaGetSymbolAddress((void**)&wt3, wt3_buf);
    float* out = (float*)d_out;

    int nb = (n + 255) / 256;
    int eb = (e + 255) / 256;
    int scan_blocks = (n + SCAN_B - 1) / SCAN_B;

    constexpr int SMEM1 = (128 * 136 + 1 * 64 * 136) * 2;
    constexpr int SMEM2 = (128 * 136 + 2 * 64 * 136) * 2;
    constexpr int SMEM3 = (64 * 136 + 2 * 128 * 136) * 2;
    cudaFuncSetAttribute(k_gemm_tc<128, float>,  cudaFuncAttributeMaxDynamicSharedMemorySize, SMEM1);
    cudaFuncSetAttribute(k_gemm_tc<128, __half>, cudaFuncAttributeMaxDynamicSharedMemorySize, SMEM2);
    cudaFuncSetAttribute(k_gemm_tc<64,  __half>, cudaFuncAttributeMaxDynamicSharedMemorySize, SMEM3);

    int tiles128 = (n + 63) / 64;
    int tiles64  = (n + 127) / 128;
    int grid128 = tiles128 < 444 ? tiles128 : 444;
    int grid64  = tiles64  < 296 ? tiles64  : 296;

    // One-time side stream + fork/join events (host infra; first call is the
    // uncaptured correctness run, so creation never happens during capture).
    static cudaStream_t s_side = [] {
        cudaStream_t s; cudaStreamCreateWithFlags(&s, cudaStreamNonBlocking); return s;
    }();
    static cudaEvent_t ev_fork = [] {
        cudaEvent_t ev; cudaEventCreateWithFlags(&ev, cudaEventDisableTiming); return ev;
    }();
    static cudaEvent_t ev_join = [] {
        cudaEvent_t ev; cudaEventCreateWithFlags(&ev, cudaEventDisableTiming); return ev;
    }();

    // prep -> hist -> blocksum_dinv on main; then fork: GEMM1 (main, needs
    // only dinv) runs concurrently with the CSR tail (side, needs only deg).
    k_prep<<<nb, 256>>>(W1, W2, W3, n);                                     // 1
    k_hist<<<eb, 256>>>(dst, e);                                            // 2
    k_blocksum_dinv<<<scan_blocks, SCAN_B>>>(n);                            // 3
    cudaEventRecord(ev_fork, 0);
    cudaStreamWaitEvent(s_side, ev_fork, 0);

    k_gemm_tc<128, float><<<grid128, 256, SMEM1>>>(x, wt1, g, n, tiles128); // 4 (main)

    k_scan_blocksums<<<1, MAX_SCAN_BLOCKS, 0, s_side>>>(scan_blocks, n, e); // side
    k_block_scan<<<scan_blocks, SCAN_B, 0, s_side>>>(n);                    // side
    k_scatter<<<eb, 256, 0, s_side>>>(src, dst, e);                         // side
    cudaEventRecord(ev_join, s_side);
    cudaStreamWaitEvent(0, ev_join, 0);
    // joined: agg1 needs g (main) + CSR (side).

    int agg_blocks = (n * 32 + 255) / 256;

    k_aggregate<128, true, __half><<<agg_blocks, 256>>>(g, b1, agg, n);

    k_gemm_tc<128, __half><<<grid128, 256, SMEM2>>>(agg, wt2, g, n, tiles128);
    k_aggregate<128, true, __half><<<agg_blocks, 256>>>(g, b2, agg, n);

    k_gemm_tc<64, __half><<<grid64, 256, SMEM3>>>(agg, wt3, g, n, tiles64);
    k_aggregate<64, false, float><<<agg_blocks, 256>>>(g, b3, out, n);
}